// round 15
// baseline (speedup 1.0000x reference)
#include <cuda_runtime.h>
#include <cuda_bf16.h>
#include <float.h>
#include <math.h>

#define NPTS 4096
#define NB 2
#define NN 8192
#define DD 64
#define KK 5
#define NKB (NPTS*KK)      /* 20480 flat (k-major) per batch */
#define EDGES (NB*NKB)     /* 40960 edges */

/* ---------------- scratch (device globals; no allocation allowed) -------- */
__device__ float         g_xf1[NN*DD];
__device__ float         g_ge1[NN*DD];
__device__ float         g_ge2[NN*DD];
__device__ float         g_sq [NN];
__device__ int           g_idx1[NB*NKB];
__device__ int           g_idx2[NB*NKB];
__device__ float         g_A  [NN*DD];
__device__ float         g_B  [NN*DD];
__device__ unsigned      g_acc[NN*DD];
__device__ float         g_x2 [NN*DD];
__device__ __nv_bfloat16 g_g3 [NN*192];   /* 3-way bf16 split of embeddings */

/* ordered float<->uint key (monotone map, finite floats) */
__device__ __forceinline__ unsigned fkey(float f) {
    unsigned u = __float_as_uint(f);
    return u ^ ((unsigned)(((int)u) >> 31) | 0x80000000u);
}
__device__ __forceinline__ float fdec(unsigned u) {
    unsigned v = u ^ ((u & 0x80000000u) ? 0x80000000u : 0xFFFFFFFFu);
    return __uint_as_float(v);
}
#define NEG_MAX_KEY 0x00800000u   /* fkey(-FLT_MAX) */

/* cp.async helpers (still used by prologue-free kernels) */
__device__ __forceinline__ void cp_async16(void* smem_dst, const void* gsrc) {
    unsigned s = (unsigned)__cvta_generic_to_shared(smem_dst);
    asm volatile("cp.async.ca.shared.global [%0], [%1], 16;" :: "r"(s), "l"(gsrc));
}
__device__ __forceinline__ void cp_commit() {
    asm volatile("cp.async.commit_group;" ::: "memory");
}
template<int N> __device__ __forceinline__ void cp_wait() {
    asm volatile("cp.async.wait_group %0;" :: "n"(N) : "memory");
}

/* TMA bulk copy gmem->smem with mbarrier complete_tx */
__device__ __forceinline__ void cp_bulk(unsigned dst_smem, const void* src, unsigned bytes,
                                        unsigned mbar) {
    asm volatile("cp.async.bulk.shared::cta.global.mbarrier::complete_tx::bytes "
                 "[%0], [%1], %2, [%3];"
                 :: "r"(dst_smem), "l"(src), "r"(bytes), "r"(mbar) : "memory");
}
__device__ __forceinline__ void mbar_init(unsigned mbar, unsigned count) {
    asm volatile("mbarrier.init.shared.b64 [%0], %1;" :: "r"(mbar), "r"(count) : "memory");
}
__device__ __forceinline__ void mbar_expect_tx(unsigned mbar, unsigned tx) {
    asm volatile("mbarrier.arrive.expect_tx.shared.b64 _, [%0], %1;"
                 :: "r"(mbar), "r"(tx) : "memory");
}
__device__ __forceinline__ void mbar_wait(unsigned mbar, unsigned parity) {
    asm volatile("{\n\t"
                 ".reg .pred P1;\n\t"
                 "WAIT_%=:\n\t"
                 "mbarrier.try_wait.parity.acquire.cta.shared::cta.b64 P1, [%0], %1, 0x989680;\n\t"
                 "@P1 bra.uni DONE_%=;\n\t"
                 "bra.uni WAIT_%=;\n\t"
                 "DONE_%=:\n\t"
                 "}" :: "r"(mbar), "r"(parity) : "memory");
}

/* ldmatrix x4 (b16), shared address precomputed by caller */
__device__ __forceinline__ void ldsm4(unsigned &r0, unsigned &r1, unsigned &r2, unsigned &r3,
                                      unsigned saddr) {
    asm volatile("ldmatrix.sync.aligned.m8n8.x4.shared.b16 {%0,%1,%2,%3}, [%4];"
                 : "=r"(r0), "=r"(r1), "=r"(r2), "=r"(r3) : "r"(saddr));
}

/* mma m16n8k16 row.col f32 <- bf16 x bf16 + f32 */
__device__ __forceinline__ void mma16816(float* c, unsigned a0, unsigned a1,
                                         unsigned a2, unsigned a3,
                                         unsigned b0, unsigned b1) {
    asm volatile("mma.sync.aligned.m16n8k16.row.col.f32.bf16.bf16.f32 "
                 "{%0,%1,%2,%3}, {%4,%5,%6,%7}, {%8,%9}, {%0,%1,%2,%3};"
                 : "+f"(c[0]), "+f"(c[1]), "+f"(c[2]), "+f"(c[3])
                 : "r"(a0), "r"(a1), "r"(a2), "r"(a3), "r"(b0), "r"(b1));
}

/* ---------------- generic small GEMM: Y = act(X@W + b), 64 rows/block ---- */
template<int NCOL>
__global__ __launch_bounds__(256) void gemm_act(
    const float* __restrict__ X1, int k1,
    const float* __restrict__ X2, int k2,
    const float* __restrict__ W, const float* __restrict__ bias,
    float* __restrict__ Y, int act)
{
    constexpr int G  = NCOL / 4;
    constexpr int TY = 256 / G;
    constexpr int R  = 64 / TY;
    __shared__ float Ws[128 * NCOL];
    __shared__ float Xs[64 * 33];
    __shared__ float bs[NCOL];
    const int t = threadIdx.x;
    const int rowBase = blockIdx.x * 64;
    const int KD = k1 + k2;

    for (int f = t; f < KD * NCOL; f += 256) Ws[f] = W[f];
    if (t < NCOL) bs[t] = (bias != nullptr) ? bias[t] : 0.0f;

    const int tx = t % G, ty = t / G;
    float acc[R][4];
#pragma unroll
    for (int rr = 0; rr < R; rr++) { acc[rr][0]=0.f; acc[rr][1]=0.f; acc[rr][2]=0.f; acc[rr][3]=0.f; }

    for (int ko = 0; ko < KD; ko += 32) {
        const float* Xsrc; int stride, koff;
        if (ko < k1) { Xsrc = X1; stride = k1; koff = ko; }
        else         { Xsrc = X2; stride = k2; koff = ko - k1; }
        __syncthreads();
        for (int f = t; f < 64 * 32; f += 256) {
            int r = f >> 5, k = f & 31;
            Xs[r * 33 + k] = Xsrc[(rowBase + r) * stride + koff + k];
        }
        __syncthreads();
#pragma unroll
        for (int k = 0; k < 32; k++) {
            float4 w4 = *(const float4*)(Ws + (ko + k) * NCOL + tx * 4);
#pragma unroll
            for (int rr = 0; rr < R; rr++) {
                float xv = Xs[(ty + rr * TY) * 33 + k];
                acc[rr][0] += xv * w4.x; acc[rr][1] += xv * w4.y;
                acc[rr][2] += xv * w4.z; acc[rr][3] += xv * w4.w;
            }
        }
    }
#pragma unroll
    for (int rr = 0; rr < R; rr++) {
        int r = rowBase + ty + rr * TY;
        float4 o;
        o.x = acc[rr][0] + bs[tx*4+0];
        o.y = acc[rr][1] + bs[tx*4+1];
        o.z = acc[rr][2] + bs[tx*4+2];
        o.w = acc[rr][3] + bs[tx*4+3];
        if (act == 1) {          /* leaky relu 0.1 */
            o.x = o.x > 0.f ? o.x : 0.1f*o.x; o.y = o.y > 0.f ? o.y : 0.1f*o.y;
            o.z = o.z > 0.f ? o.z : 0.1f*o.z; o.w = o.w > 0.f ? o.w : 0.1f*o.w;
        } else if (act == 2) {   /* relu */
            o.x = fmaxf(o.x,0.f); o.y = fmaxf(o.y,0.f);
            o.z = fmaxf(o.z,0.f); o.w = fmaxf(o.w,0.f);
        }
        *(float4*)(Y + r * NCOL + tx * 4) = o;
    }
}

/* -------- fused EdgeConv GEMMs: A = X@(Wtop-Wbot)+bias, B = X@Wbot ------- */
__global__ __launch_bounds__(256) void gemm_ab(
    const float* __restrict__ X, const float* __restrict__ Wc,
    const float* __restrict__ bias, float* __restrict__ A, float* __restrict__ B)
{
    __shared__ float Ws[128 * 64];
    __shared__ float Xs[64 * 33];
    __shared__ float bs[64];
    const int t = threadIdx.x;
    const int rowBase = blockIdx.x * 64;
    for (int f = t; f < 128 * 64; f += 256) Ws[f] = Wc[f];
    if (t < 64) bs[t] = bias[t];

    const int tx = t % 16, ty = t / 16;        /* 16 col-groups x 16 rows */
    float aT[4][4], aB[4][4];
#pragma unroll
    for (int rr = 0; rr < 4; rr++)
#pragma unroll
        for (int c = 0; c < 4; c++) { aT[rr][c] = 0.f; aB[rr][c] = 0.f; }

    for (int ko = 0; ko < 64; ko += 32) {
        __syncthreads();
        for (int f = t; f < 64 * 32; f += 256) {
            int r = f >> 5, k = f & 31;
            Xs[r * 33 + k] = X[(rowBase + r) * 64 + ko + k];
        }
        __syncthreads();
#pragma unroll
        for (int k = 0; k < 32; k++) {
            float4 wt = *(const float4*)(Ws + (ko + k) * 64 + tx * 4);
            float4 wb = *(const float4*)(Ws + (64 + ko + k) * 64 + tx * 4);
#pragma unroll
            for (int rr = 0; rr < 4; rr++) {
                float xv = Xs[(ty + rr * 16) * 33 + k];
                aT[rr][0] = fmaf(xv, wt.x, aT[rr][0]); aT[rr][1] = fmaf(xv, wt.y, aT[rr][1]);
                aT[rr][2] = fmaf(xv, wt.z, aT[rr][2]); aT[rr][3] = fmaf(xv, wt.w, aT[rr][3]);
                aB[rr][0] = fmaf(xv, wb.x, aB[rr][0]); aB[rr][1] = fmaf(xv, wb.y, aB[rr][1]);
                aB[rr][2] = fmaf(xv, wb.z, aB[rr][2]); aB[rr][3] = fmaf(xv, wb.w, aB[rr][3]);
            }
        }
    }
#pragma unroll
    for (int rr = 0; rr < 4; rr++) {
        int r = rowBase + ty + rr * 16;
        float4 ao, bo;
        ao.x = aT[rr][0] - aB[rr][0] + bs[tx*4+0];
        ao.y = aT[rr][1] - aB[rr][1] + bs[tx*4+1];
        ao.z = aT[rr][2] - aB[rr][2] + bs[tx*4+2];
        ao.w = aT[rr][3] - aB[rr][3] + bs[tx*4+3];
        bo.x = aB[rr][0]; bo.y = aB[rr][1]; bo.z = aB[rr][2]; bo.w = aB[rr][3];
        *(float4*)(A + r * 64 + tx * 4) = ao;
        *(float4*)(B + r * 64 + tx * 4) = bo;
    }
}

/* -------- prep: sum of squares + 3-way bf16 split (FROZEN arithmetic) ---- */
__global__ void prep3_kernel(const float* __restrict__ ge,
                             __nv_bfloat16* __restrict__ g3,
                             float* __restrict__ sq)
{
    int i = blockIdx.x * 256 + threadIdx.x;
    if (i >= NN * DD) return;
    int r = i >> 6, d = i & 63;
    float v = ge[i];
    __nv_bfloat16 b0 = __float2bfloat16_rn(v);
    float r1 = v - __bfloat162float(b0);
    __nv_bfloat16 b1 = __float2bfloat16_rn(r1);
    float r2 = r1 - __bfloat162float(b1);
    __nv_bfloat16 b2 = __float2bfloat16_rn(r2);
    __nv_bfloat16* row = g3 + (size_t)r * 192;
    row[d] = b0; row[64 + d] = b1; row[128 + d] = b2;

    if (d == 0) {   /* one thread per row does the sq reduction */
        const float4* p = (const float4*)(ge + r * DD);
        float s0=0.f,s1=0.f,s2=0.f,s3=0.f;
#pragma unroll
        for (int d4 = 0; d4 < 16; d4++) {
            float4 w = p[d4];
            s0 += w.x*w.x; s1 += w.y*w.y; s2 += w.z*w.z; s3 += w.w*w.w;
        }
        sq[r] = (s0+s1)+(s2+s3);
    }
}

/* ---------------- KNN via bf16-split tensor-core GEMM --------------------
   CTA: 32 queries x all 4096 points; 8 warps = 2 m-warps x 4 n-warps;
   256 threads, OCCUPANCY 2. 4-deep Ps ring, distance-2 prefetch, ONE
   barrier per tile. NEW: tile fills via cp.async.bulk (TMA/UBLKCP, 65
   bulk copies per tile issued by warp 0) + 4-slot mbarrier ring with
   expect_tx/parity waits -- removes ~196k LDGSTS/SM of issue pressure.
   Same bytes to the same smem addresses (stride-400 rows preserved);
   ldsm/HMMA/epilogue untouched -> BIT-IDENTICAL results to R6..R14.
   Slot-reuse safety: fill(tt+2) issued only after passing barrier(tt-1),
   which follows every warp's mma(tt-2) and mbar-wait(tt-2).              */
#define KNN_SMEM 103680
__global__ __launch_bounds__(256, 2) void knn_mma_kernel(
    const __nv_bfloat16* __restrict__ g3, const float* __restrict__ sqg,
    int* __restrict__ idxflat)
{
    extern __shared__ char sm[];
    char*  Ps  = sm;                        /* 4 x 64 x 400B ring (Qs overlays slot 0) */
    float* sqq = (float*)(sm + 103424);     /* 32 floats                  */

    const int tid  = threadIdx.x;
    const int lane = tid & 31, w = tid >> 5;
    const int mwarp = w & 1, nwarp = w >> 1;     /* 2 x 4 */
    const int mbase = mwarp * 16;
    const int qbase = blockIdx.x * 32;
    const int bb    = blockIdx.y;
    const char*  g3b = (const char*)(g3 + (size_t)bb * NPTS * 192);
    const float* sqb = sqg + bb * NPTS;
    const char*  sqbb = (const char*)sqb;

    const unsigned Ps32   = (unsigned)__cvta_generic_to_shared(Ps);
    const unsigned sqpA   = Ps32 + 102400;       /* 4-slot ring x 64 floats */
    const unsigned mbA    = Ps32 + 103552;       /* 4 mbarriers (8B each)   */
    float* sqp = (float*)(sm + 102400);

    /* stage queries into ring slot 0 area (transient): 32 rows x 384B */
    for (int f = tid; f < 768; f += 256) {
        int r = f / 24, c = f % 24;
        *(uint4*)(Ps + r * 400 + c * 16) =
            *(const uint4*)(g3b + (size_t)(qbase + r) * 384 + c * 16);
    }
    if (tid < 32) sqq[tid] = sqb[qbase + tid];
    if (tid == 0) {
#pragma unroll
        for (int s = 0; s < 4; s++) mbar_init(mbA + s * 8, 1);
    }
    __syncthreads();

    /* per-lane ldmatrix addresses */
    const int aRow = mbase + ((lane >> 3) & 1) * 8 + (lane & 7);
    const unsigned aAddr = Ps32 + aRow * 400 + ((lane >> 4) & 1) * 16;
    const int bRow = ((lane >> 4) & 1) * 8 + (lane & 7);
    const unsigned bOff = (unsigned)((nwarp * 16 + bRow) * 400 + ((lane >> 3) & 1) * 16);

    /* hoist A fragments: 3 splits x 4 k-steps, tile-invariant */
    unsigned afr[3][4][4];
#pragma unroll
    for (int pa = 0; pa < 3; pa++)
#pragma unroll
        for (int ks = 0; ks < 4; ks++)
            ldsm4(afr[pa][ks][0], afr[pa][ks][1], afr[pa][ks][2], afr[pa][ks][3],
                  aAddr + pa * 128 + ks * 32);

    const float sqiA = sqq[mbase + (lane >> 2)];
    const float sqiB = sqq[mbase + (lane >> 2) + 8];

    /* all warps done reading Qs -> ring may overwrite it */
    __syncthreads();

    /* prologue: fill tiles 0 and 1 via TMA bulk (warp 0 only) */
    if (tid < 32) {
#pragma unroll
        for (int p0 = 0; p0 < 2; p0++) {
            const unsigned mb = mbA + p0 * 8;
            if (lane == 0) mbar_expect_tx(mb, 24832u);
            __syncwarp();
            const char* src = g3b + (size_t)p0 * 24576;
            const unsigned dst = Ps32 + p0 * 25600;
            cp_bulk(dst + lane * 400,        src + (size_t)lane * 384,        384u, mb);
            cp_bulk(dst + (lane + 32) * 400, src + (size_t)(lane + 32) * 384, 384u, mb);
            if (lane == 0) cp_bulk(sqpA + p0 * 256, sqbb + (size_t)p0 * 256, 256u, mb);
        }
    }

    float tvA[5], tvB[5]; int tiA[5], tiB[5];
#pragma unroll
    for (int k = 0; k < 5; k++) {
        tvA[k] = FLT_MAX; tiA[k] = 0x7FFFFFFF;
        tvB[k] = FLT_MAX; tiB[k] = 0x7FFFFFFF;
    }

    /* FROZEN pair order (matches R6..R14 passing kernels bit-for-bit) */
    const int PA[6] = {0, 0, 1, 0, 2, 1};
    const int PB[6] = {0, 1, 0, 2, 0, 1};

    for (int tt = 0; tt < 64; tt++) {
        /* fill 2 tiles ahead into ring slot (tt+2)&3 via TMA (warp 0) */
        if (tt + 2 < 64 && tid < 32) {
            const int s = (tt + 2) & 3;
            const unsigned mb = mbA + s * 8;
            if (lane == 0) mbar_expect_tx(mb, 24832u);
            __syncwarp();
            const char* src = g3b + (size_t)(tt + 2) * 24576;
            const unsigned dst = Ps32 + s * 25600;
            cp_bulk(dst + lane * 400,        src + (size_t)lane * 384,        384u, mb);
            cp_bulk(dst + (lane + 32) * 400, src + (size_t)(lane + 32) * 384, 384u, mb);
            if (lane == 0) cp_bulk(sqpA + s * 256, sqbb + (size_t)(tt + 2) * 256, 256u, mb);
        }
        /* wait for tile tt's data (slot tt&3, use #(tt/4) -> parity) */
        mbar_wait(mbA + (tt & 3) * 8, (unsigned)((tt >> 2) & 1));
        __syncthreads();    /* ONE barrier per tile (slot-reuse safety) */

        const unsigned bB0 = Ps32 + (tt & 3) * 25600 + bOff;
        const float* SQ = sqp + (tt & 3) * 64;

        float C[2][4];
        C[0][0]=0.f; C[0][1]=0.f; C[0][2]=0.f; C[0][3]=0.f;
        C[1][0]=0.f; C[1][1]=0.f; C[1][2]=0.f; C[1][3]=0.f;

#pragma unroll
        for (int pr = 0; pr < 6; pr++) {
            const int pa = PA[pr];
            const unsigned bB = bB0 + PB[pr] * 128;
#pragma unroll
            for (int ks = 0; ks < 4; ks++) {
                unsigned b0, b1, b2, b3;
                ldsm4(b0, b1, b2, b3, bB + ks * 32);
                mma16816(C[0], afr[pa][ks][0], afr[pa][ks][1], afr[pa][ks][2], afr[pa][ks][3], b0, b1);
                mma16816(C[1], afr[pa][ks][0], afr[pa][ks][1], afr[pa][ks][2], afr[pa][ks][3], b2, b3);
            }
        }

        /* epilogue: 8 dots per lane -> distances -> top-5 insert */
#pragma unroll
        for (int nb = 0; nb < 2; nb++) {
            const int col0 = nwarp * 16 + nb * 8 + (lane & 3) * 2;
            const float sp0 = SQ[col0], sp1 = SQ[col0 + 1];
            const int id0 = tt * 64 + col0;
            float d00 = fmaxf(fmaf(-2.f, C[nb][0], sqiA + sp0), 0.f);
            float d01 = fmaxf(fmaf(-2.f, C[nb][1], sqiA + sp1), 0.f);
            float d10 = fmaxf(fmaf(-2.f, C[nb][2], sqiB + sp0), 0.f);
            float d11 = fmaxf(fmaf(-2.f, C[nb][3], sqiB + sp1), 0.f);
#define INS(TV, TI, DV, IDX)                                                   \
            if (DV < TV[4]) {                                                  \
                TV[4] = DV; TI[4] = IDX;                                       \
                _Pragma("unroll")                                              \
                for (int s2 = 4; s2 > 0; s2--) {                               \
                    if (TV[s2] < TV[s2-1]) {                                   \
                        float fv = TV[s2]; TV[s2] = TV[s2-1]; TV[s2-1] = fv;   \
                        int  iv = TI[s2]; TI[s2] = TI[s2-1]; TI[s2-1] = iv;    \
                    }                                                          \
                }                                                              \
            }
            INS(tvA, tiA, d00, id0)
            INS(tvA, tiA, d01, id0 + 1)
            INS(tvB, tiB, d10, id0)
            INS(tvB, tiB, d11, id0 + 1)
#undef INS
        }
    }

    /* block merge: per query 16 lanes x 5 candidates; stride 81 */
    __syncthreads();
    float* cv = (float*)sm;
    int*   ci = (int*)(sm + 32 * 81 * 4);
    {
        const int slot = nwarp * 20 + (lane & 3) * 5;
        const int qA = mbase + (lane >> 2);
#pragma unroll
        for (int k = 0; k < 5; k++) {
            cv[qA * 81 + slot + k] = tvA[k];
            ci[qA * 81 + slot + k] = tiA[k];
            cv[(qA + 8) * 81 + slot + k] = tvB[k];
            ci[(qA + 8) * 81 + slot + k] = tiB[k];
        }
    }
    __syncthreads();
    if (tid < 32) {
        float bv[5]; int bi[5];
#pragma unroll
        for (int k = 0; k < 5; k++) { bv[k] = FLT_MAX; bi[k] = 0x7FFFFFFF; }
        for (int e = 0; e < 80; e++) {
            float v = cv[tid * 81 + e];
            int   i = ci[tid * 81 + e];
            if (v < bv[4] || (v == bv[4] && i < bi[4])) {
                bv[4] = v; bi[4] = i;
#pragma unroll
                for (int s2 = 4; s2 > 0; s2--) {
                    if (bv[s2] < bv[s2-1] || (bv[s2] == bv[s2-1] && bi[s2] < bi[s2-1])) {
                        float fv = bv[s2]; bv[s2] = bv[s2-1]; bv[s2-1] = fv;
                        int  iv = bi[s2]; bi[s2] = bi[s2-1]; bi[s2-1] = iv;
                    }
                }
            }
        }
#pragma unroll
        for (int k = 0; k < 5; k++)
            idxflat[bb * NKB + k * NPTS + qbase + tid] = bi[k];
    }
}

/* ---------------- logprobs: lp[b,i,kk,layer] ----------------------------- */
__global__ void lp_kernel(const float* __restrict__ ge, const int* __restrict__ idxflat,
                          const float* __restrict__ tptr, float* __restrict__ outp, int layer)
{
    int gid = blockIdx.x * blockDim.x + threadIdx.x;
    if (gid >= NB * NKB) return;
    int bb = gid / NKB;
    int m  = gid - bb * NKB;
    float tval = fminf(fmaxf(tptr[0], -5.0f), 5.0f);
    float t = expf(tval);
    int nb  = idxflat[bb * NKB + m];
    int ctr = m / KK;
    int kk  = m - ctr * KK;
    const float4* pa = (const float4*)(ge + (bb * NPTS + nb) * DD);
    const float4* pb = (const float4*)(ge + (bb * NPTS + ctr) * DD);
    float s = 0.f;
#pragma unroll
    for (int d4 = 0; d4 < 16; d4++) {
        float4 a = pa[d4], b4 = pb[d4];
        float dx=a.x-b4.x, dy=a.y-b4.y, dz=a.z-b4.z, dw=a.w-b4.w;
        s += dx*dx + dy*dy + dz*dz + dw*dw;
    }
    outp[((bb * NPTS + ctr) * KK + kk) * 2 + layer] = -s * t;
}

/* ---------------- scatter-max edge conv --------------------------------- */
__global__ void init_acc_kernel(unsigned* __restrict__ acc) {
    int i = blockIdx.x * blockDim.x + threadIdx.x;
    if (i < NN * DD) acc[i] = NEG_MAX_KEY;
}

__global__ void scatter_kernel(const int* __restrict__ idxflat,
                               const float* __restrict__ A, const float* __restrict__ B,
                               unsigned* __restrict__ acc)
{
    int gid = blockIdx.x * blockDim.x + threadIdx.x;
    if (gid >= EDGES * 16) return;
    int q  = gid >> 4;
    int cg = gid & 15;
    int mq = q >> 2;
    int bb = (q >> 1) & 1;
    int c  = q & 1;
    int m_s = mq;
    int m_d = mq + NKB / 2;
    int srcv = (c == 0) ? idxflat[bb * NKB + m_s] : (m_s / KK);
    int dstv = (c == 0) ? idxflat[bb * NKB + m_d] : (m_d / KK);
    srcv += bb * NPTS;
    dstv += bb * NPTS;
    float4 av = ((const float4*)A)[dstv * 16 + cg];
    float4 bv = ((const float4*)B)[srcv * 16 + cg];
    unsigned* base = acc + dstv * DD + cg * 4;
    atomicMax(base + 0, fkey(av.x + bv.x));
    atomicMax(base + 1, fkey(av.y + bv.y));
    atomicMax(base + 2, fkey(av.z + bv.z));
    atomicMax(base + 3, fkey(av.w + bv.w));
}

/* decode + relu; also re-initializes acc for the next layer (saves launch) */
__global__ void decode_relu_kernel(unsigned* __restrict__ acc, float* __restrict__ y) {
    int i = blockIdx.x * blockDim.x + threadIdx.x;
    if (i < NN * DD) {
        unsigned u = acc[i];
        y[i] = fmaxf(fdec(u), 0.0f);
        acc[i] = NEG_MAX_KEY;
    }
}

/* ------- fused head: decode(acc) -> lrelu(x@Wf1+b)@Wf2+b (no x3 pass) --- */
__global__ __launch_bounds__(128) void head_kernel(
    const unsigned* __restrict__ acc,
    const float* __restrict__ Wf1, const float* __restrict__ bf1,
    const float* __restrict__ Wf2, const float* __restrict__ bf2,
    float* __restrict__ out)
{
    __shared__ float w1[64 * 32];
    __shared__ float w2[32 * 8];
    __shared__ float b1s[32], b2s[8];
    int t = threadIdx.x;
    for (int f = t; f < 2048; f += 128) w1[f] = Wf1[f];
    for (int f = t; f < 256;  f += 128) w2[f] = Wf2[f];
    if (t < 32) b1s[t] = bf1[t];
    if (t < 8)  b2s[t] = bf2[t];
    __syncthreads();
    int r = blockIdx.x * 128 + t;
    if (r >= NN) return;
    float xr[64];
#pragma unroll
    for (int d4 = 0; d4 < 16; d4++) {
        uint4 v = ((const uint4*)(acc + r * DD))[d4];
        xr[d4*4+0] = fmaxf(fdec(v.x), 0.0f);
        xr[d4*4+1] = fmaxf(fdec(v.y), 0.0f);
        xr[d4*4+2] = fmaxf(fdec(v.z), 0.0f);
        xr[d4*4+3] = fmaxf(fdec(v.w), 0.0f);
    }
    float o[8];
#pragma unroll
    for (int k = 0; k < 8; k++) o[k] = b2s[k];
    for (int jj = 0; jj < 32; jj++) {
        float h0=0.f,h1=0.f,h2=0.f,h3=0.f;
#pragma unroll
        for (int k = 0; k < 64; k += 4) {
            h0 += xr[k+0] * w1[(k+0)*32 + jj];
            h1 += xr[k+1] * w1[(k+1)*32 + jj];
            h2 += xr[k+2] * w1[(k+2)*32 + jj];
            h3 += xr[k+3] * w1[(k+3)*32 + jj];
        }
        float h = ((h0+h1)+(h2+h3)) + b1s[jj];
        h = h > 0.f ? h : 0.1f * h;
#pragma unroll
        for (int k = 0; k < 8; k++) o[k] += h * w2[jj*8 + k];
    }
#pragma unroll
    for (int k = 0; k < 8; k++) out[r * 8 + k] = o[k];
}

/* ---------------- launch ------------------------------------------------- */
extern "C" void kernel_launch(void* const* d_in, const int* in_sizes, int n_in,
                              void* d_out, int out_size)
{
    const float* x     = (const float*)d_in[0];
    const float* W_pre = (const float*)d_in[1];
    const float* b_pre = (const float*)d_in[2];
    const float* W_d1  = (const float*)d_in[3];
    const float* b_d1  = (const float*)d_in[4];
    const float* t1    = (const float*)d_in[5];
    const float* W_c1  = (const float*)d_in[6];
    const float* b_c1  = (const float*)d_in[7];
    const float* W_d2  = (const float*)d_in[8];
    const float* b_d2  = (const float*)d_in[9];
    const float* t2    = (const float*)d_in[10];
    const float* W_c2  = (const float*)d_in[11];
    const float* b_c2  = (const float*)d_in[12];
    const float* W_f1  = (const float*)d_in[13];
    const float* b_f1  = (const float*)d_in[14];
    const float* W_f2  = (const float*)d_in[15];
    const float* b_f2  = (const float*)d_in[16];

    float* out = (float*)d_out;            /* [2,4096,8] = 65536 floats   */
    float* lp  = out + NN * 8;             /* [2,4096,5,2] = 81920 floats */

    float *p_xf1, *p_ge1, *p_ge2, *p_sq, *p_A, *p_B, *p_x2;
    int *p_idx1, *p_idx2;
    unsigned *p_acc;
    __nv_bfloat16 *p_g3;
    cudaGetSymbolAddress((void**)&p_xf1,  g_xf1);
    cudaGetSymbolAddress((void**)&p_ge1,  g_ge1);
    cudaGetSymbolAddress((void**)&p_ge2,  g_ge2);
    cudaGetSymbolAddress((void**)&p_sq,   g_sq);
    cudaGetSymbolAddress((void**)&p_idx1, g_idx1);
    cudaGetSymbolAddress((void**)&p_idx2, g_idx2);
    cudaGetSymbolAddress((void**)&p_A,    g_A);
    cudaGetSymbolAddress((void**)&p_B,    g_B);
    cudaGetSymbolAddress((void**)&p_acc,  g_acc);
    cudaGetSymbolAddress((void**)&p_x2,   g_x2);
    cudaGetSymbolAddress((void**)&p_g3,   g_g3);

    cudaFuncSetAttribute(knn_mma_kernel, cudaFuncAttributeMaxDynamicSharedMemorySize, KNN_SMEM);

    const float* nul = nullptr;
    dim3 knn_grid(NPTS / 32, NB);

    /* pre MLP + embed 1 */
    gemm_act<64><<<NN/64, 256>>>(x,     32, nul, 0, W_pre, b_pre, p_xf1, 1);
    gemm_act<64><<<NN/64, 256>>>(p_xf1, 64, nul, 0, W_d1,  b_d1,  p_ge1, 0);

    /* knn 1 + lp 1 */
    prep3_kernel<<<(NN*DD)/256, 256>>>(p_ge1, p_g3, p_sq);
    knn_mma_kernel<<<knn_grid, 256, KNN_SMEM>>>(p_g3, p_sq, p_idx1);
    lp_kernel<<<(NB*NKB)/256, 256>>>(p_ge1, p_idx1, t1, lp, 0);

    /* edge conv 1 */
    gemm_ab<<<NN/64, 256>>>(p_xf1, W_c1, b_c1, p_A, p_B);
    init_acc_kernel<<<(NN*DD)/256, 256>>>(p_acc);
    scatter_kernel<<<(EDGES*16)/256, 256>>>(p_idx1, p_A, p_B, p_acc);
    decode_relu_kernel<<<(NN*DD)/256, 256>>>(p_acc, p_x2);

    /* embed 2 on concat[ge1, x2] */
    gemm_act<64><<<NN/64, 256>>>(p_ge1, 64, p_x2, 64, W_d2, b_d2, p_ge2, 0);

    /* knn 2 + lp 2 */
    prep3_kernel<<<(NN*DD)/256, 256>>>(p_ge2, p_g3, p_sq);
    knn_mma_kernel<<<knn_grid, 256, KNN_SMEM>>>(p_g3, p_sq, p_idx2);
    lp_kernel<<<(NB*NKB)/256, 256>>>(p_ge2, p_idx2, t2, lp, 1);

    /* edge conv 2 (acc already re-initialized by decode_relu of layer 1) */
    gemm_ab<<<NN/64, 256>>>(p_x2, W_c2, b_c2, p_A, p_B);
    scatter_kernel<<<(EDGES*16)/256, 256>>>(p_idx2, p_A, p_B, p_acc);

    /* head (decode fused) */
    head_kernel<<<NN/128, 128>>>(p_acc, W_f1, b_f1, W_f2, b_f2, out);
}

// round 16
// speedup vs baseline: 1.3058x; 1.3058x over previous
#include <cuda_runtime.h>
#include <cuda_bf16.h>
#include <float.h>
#include <math.h>

#define NPTS 4096
#define NB 2
#define NN 8192
#define DD 64
#define KK 5
#define NKB (NPTS*KK)      /* 20480 flat (k-major) per batch */
#define EDGES (NB*NKB)     /* 40960 edges */

/* ---------------- scratch (device globals; no allocation allowed) -------- */
__device__ float         g_xf1[NN*DD];
__device__ float         g_ge1[NN*DD];
__device__ float         g_ge2[NN*DD];
__device__ float         g_sq [NN];
__device__ int           g_idx1[NB*NKB];
__device__ int           g_idx2[NB*NKB];
__device__ float         g_A  [NN*DD];
__device__ float         g_B  [NN*DD];
__device__ unsigned      g_acc[NN*DD];
__device__ float         g_x2 [NN*DD];
__device__ __nv_bfloat16 g_g3 [NN*192];   /* 3-way bf16 split of embeddings */
__device__ float         g_pv [NN*10];    /* partial top-5 vals (2 halves)  */
__device__ int           g_pi [NN*10];    /* partial top-5 idx  (2 halves)  */

/* ordered float<->uint key (monotone map, finite floats) */
__device__ __forceinline__ unsigned fkey(float f) {
    unsigned u = __float_as_uint(f);
    return u ^ ((unsigned)(((int)u) >> 31) | 0x80000000u);
}
__device__ __forceinline__ float fdec(unsigned u) {
    unsigned v = u ^ ((u & 0x80000000u) ? 0x80000000u : 0xFFFFFFFFu);
    return __uint_as_float(v);
}
#define NEG_MAX_KEY 0x00800000u   /* fkey(-FLT_MAX) */

/* cp.async helpers */
__device__ __forceinline__ void cp_async16(void* smem_dst, const void* gsrc) {
    unsigned s = (unsigned)__cvta_generic_to_shared(smem_dst);
    asm volatile("cp.async.ca.shared.global [%0], [%1], 16;" :: "r"(s), "l"(gsrc));
}
__device__ __forceinline__ void cp_async16s(unsigned smem_addr, const void* gsrc) {
    asm volatile("cp.async.ca.shared.global [%0], [%1], 16;" :: "r"(smem_addr), "l"(gsrc));
}
__device__ __forceinline__ void cp_commit() {
    asm volatile("cp.async.commit_group;" ::: "memory");
}
template<int N> __device__ __forceinline__ void cp_wait() {
    asm volatile("cp.async.wait_group %0;" :: "n"(N) : "memory");
}

/* ldmatrix x4 (b16), shared address precomputed by caller */
__device__ __forceinline__ void ldsm4(unsigned &r0, unsigned &r1, unsigned &r2, unsigned &r3,
                                      unsigned saddr) {
    asm volatile("ldmatrix.sync.aligned.m8n8.x4.shared.b16 {%0,%1,%2,%3}, [%4];"
                 : "=r"(r0), "=r"(r1), "=r"(r2), "=r"(r3) : "r"(saddr));
}

/* mma m16n8k16 row.col f32 <- bf16 x bf16 + f32 */
__device__ __forceinline__ void mma16816(float* c, unsigned a0, unsigned a1,
                                         unsigned a2, unsigned a3,
                                         unsigned b0, unsigned b1) {
    asm volatile("mma.sync.aligned.m16n8k16.row.col.f32.bf16.bf16.f32 "
                 "{%0,%1,%2,%3}, {%4,%5,%6,%7}, {%8,%9}, {%0,%1,%2,%3};"
                 : "+f"(c[0]), "+f"(c[1]), "+f"(c[2]), "+f"(c[3])
                 : "r"(a0), "r"(a1), "r"(a2), "r"(a3), "r"(b0), "r"(b1));
}

/* ---------------- generic small GEMM: Y = act(X@W + b), 64 rows/block ---- */
template<int NCOL>
__global__ __launch_bounds__(256) void gemm_act(
    const float* __restrict__ X1, int k1,
    const float* __restrict__ X2, int k2,
    const float* __restrict__ W, const float* __restrict__ bias,
    float* __restrict__ Y, int act)
{
    constexpr int G  = NCOL / 4;
    constexpr int TY = 256 / G;
    constexpr int R  = 64 / TY;
    __shared__ float Ws[128 * NCOL];
    __shared__ float Xs[64 * 33];
    __shared__ float bs[NCOL];
    const int t = threadIdx.x;
    const int rowBase = blockIdx.x * 64;
    const int KD = k1 + k2;

    for (int f = t; f < KD * NCOL; f += 256) Ws[f] = W[f];
    if (t < NCOL) bs[t] = (bias != nullptr) ? bias[t] : 0.0f;

    const int tx = t % G, ty = t / G;
    float acc[R][4];
#pragma unroll
    for (int rr = 0; rr < R; rr++) { acc[rr][0]=0.f; acc[rr][1]=0.f; acc[rr][2]=0.f; acc[rr][3]=0.f; }

    for (int ko = 0; ko < KD; ko += 32) {
        const float* Xsrc; int stride, koff;
        if (ko < k1) { Xsrc = X1; stride = k1; koff = ko; }
        else         { Xsrc = X2; stride = k2; koff = ko - k1; }
        __syncthreads();
        for (int f = t; f < 64 * 32; f += 256) {
            int r = f >> 5, k = f & 31;
            Xs[r * 33 + k] = Xsrc[(rowBase + r) * stride + koff + k];
        }
        __syncthreads();
#pragma unroll
        for (int k = 0; k < 32; k++) {
            float4 w4 = *(const float4*)(Ws + (ko + k) * NCOL + tx * 4);
#pragma unroll
            for (int rr = 0; rr < R; rr++) {
                float xv = Xs[(ty + rr * TY) * 33 + k];
                acc[rr][0] += xv * w4.x; acc[rr][1] += xv * w4.y;
                acc[rr][2] += xv * w4.z; acc[rr][3] += xv * w4.w;
            }
        }
    }
#pragma unroll
    for (int rr = 0; rr < R; rr++) {
        int r = rowBase + ty + rr * TY;
        float4 o;
        o.x = acc[rr][0] + bs[tx*4+0];
        o.y = acc[rr][1] + bs[tx*4+1];
        o.z = acc[rr][2] + bs[tx*4+2];
        o.w = acc[rr][3] + bs[tx*4+3];
        if (act == 1) {          /* leaky relu 0.1 */
            o.x = o.x > 0.f ? o.x : 0.1f*o.x; o.y = o.y > 0.f ? o.y : 0.1f*o.y;
            o.z = o.z > 0.f ? o.z : 0.1f*o.z; o.w = o.w > 0.f ? o.w : 0.1f*o.w;
        } else if (act == 2) {   /* relu */
            o.x = fmaxf(o.x,0.f); o.y = fmaxf(o.y,0.f);
            o.z = fmaxf(o.z,0.f); o.w = fmaxf(o.w,0.f);
        }
        *(float4*)(Y + r * NCOL + tx * 4) = o;
    }
}

/* -------- fused EdgeConv GEMMs: A = X@(Wtop-Wbot)+bias, B = X@Wbot ------- */
__global__ __launch_bounds__(256) void gemm_ab(
    const float* __restrict__ X, const float* __restrict__ Wc,
    const float* __restrict__ bias, float* __restrict__ A, float* __restrict__ B)
{
    __shared__ float Ws[128 * 64];
    __shared__ float Xs[64 * 33];
    __shared__ float bs[64];
    const int t = threadIdx.x;
    const int rowBase = blockIdx.x * 64;
    for (int f = t; f < 128 * 64; f += 256) Ws[f] = Wc[f];
    if (t < 64) bs[t] = bias[t];

    const int tx = t % 16, ty = t / 16;        /* 16 col-groups x 16 rows */
    float aT[4][4], aB[4][4];
#pragma unroll
    for (int rr = 0; rr < 4; rr++)
#pragma unroll
        for (int c = 0; c < 4; c++) { aT[rr][c] = 0.f; aB[rr][c] = 0.f; }

    for (int ko = 0; ko < 64; ko += 32) {
        __syncthreads();
        for (int f = t; f < 64 * 32; f += 256) {
            int r = f >> 5, k = f & 31;
            Xs[r * 33 + k] = X[(rowBase + r) * 64 + ko + k];
        }
        __syncthreads();
#pragma unroll
        for (int k = 0; k < 32; k++) {
            float4 wt = *(const float4*)(Ws + (ko + k) * 64 + tx * 4);
            float4 wb = *(const float4*)(Ws + (64 + ko + k) * 64 + tx * 4);
#pragma unroll
            for (int rr = 0; rr < 4; rr++) {
                float xv = Xs[(ty + rr * 16) * 33 + k];
                aT[rr][0] = fmaf(xv, wt.x, aT[rr][0]); aT[rr][1] = fmaf(xv, wt.y, aT[rr][1]);
                aT[rr][2] = fmaf(xv, wt.z, aT[rr][2]); aT[rr][3] = fmaf(xv, wt.w, aT[rr][3]);
                aB[rr][0] = fmaf(xv, wb.x, aB[rr][0]); aB[rr][1] = fmaf(xv, wb.y, aB[rr][1]);
                aB[rr][2] = fmaf(xv, wb.z, aB[rr][2]); aB[rr][3] = fmaf(xv, wb.w, aB[rr][3]);
            }
        }
    }
#pragma unroll
    for (int rr = 0; rr < 4; rr++) {
        int r = rowBase + ty + rr * 16;
        float4 ao, bo;
        ao.x = aT[rr][0] - aB[rr][0] + bs[tx*4+0];
        ao.y = aT[rr][1] - aB[rr][1] + bs[tx*4+1];
        ao.z = aT[rr][2] - aB[rr][2] + bs[tx*4+2];
        ao.w = aT[rr][3] - aB[rr][3] + bs[tx*4+3];
        bo.x = aB[rr][0]; bo.y = aB[rr][1]; bo.z = aB[rr][2]; bo.w = aB[rr][3];
        *(float4*)(A + r * 64 + tx * 4) = ao;
        *(float4*)(B + r * 64 + tx * 4) = bo;
    }
}

/* -------- prep: sum of squares + 3-way bf16 split (FROZEN arithmetic) ---- */
__global__ void prep3_kernel(const float* __restrict__ ge,
                             __nv_bfloat16* __restrict__ g3,
                             float* __restrict__ sq)
{
    int i = blockIdx.x * 256 + threadIdx.x;
    if (i >= NN * DD) return;
    int r = i >> 6, d = i & 63;
    float v = ge[i];
    __nv_bfloat16 b0 = __float2bfloat16_rn(v);
    float r1 = v - __bfloat162float(b0);
    __nv_bfloat16 b1 = __float2bfloat16_rn(r1);
    float r2 = r1 - __bfloat162float(b1);
    __nv_bfloat16 b2 = __float2bfloat16_rn(r2);
    __nv_bfloat16* row = g3 + (size_t)r * 192;
    row[d] = b0; row[64 + d] = b1; row[128 + d] = b2;

    if (d == 0) {   /* one thread per row does the sq reduction */
        const float4* p = (const float4*)(ge + r * DD);
        float s0=0.f,s1=0.f,s2=0.f,s3=0.f;
#pragma unroll
        for (int d4 = 0; d4 < 16; d4++) {
            float4 w = p[d4];
            s0 += w.x*w.x; s1 += w.y*w.y; s2 += w.z*w.z; s3 += w.w*w.w;
        }
        sq[r] = (s0+s1)+(s2+s3);
    }
}

/* ---------------- KNN via bf16-split tensor-core GEMM --------------------
   CTA: 32 queries x HALF the point range (2048 pts, 32 tiles); 8 warps =
   2 m-warps x 4 n-warps; 256 threads, OCCUPANCY 2. grid (128, NB, 2) =
   512 CTAs -> balanced wave over 148 SMs (~3.46 half-units/SM vs the
   previous 2.0-unit imbalanced makespan).
   R14 body otherwise unchanged: 4-deep Ps ring, distance-2 prefetch,
   ONE barrier per tile, strength-reduced fill addressing, LDGSTS fills.
   Per-element accumulation order BIT-IDENTICAL to R6..R14 passing kernels;
   per-partition ascending-index scan + global (val,idx)-lex merge (pass 2)
   is partition-invariant -> selection provably identical.                 */
#define KNN_SMEM 103680
__global__ __launch_bounds__(256, 2) void knn_mma_kernel(
    const __nv_bfloat16* __restrict__ g3, const float* __restrict__ sqg,
    float* __restrict__ pvg, int* __restrict__ pig)
{
    extern __shared__ char sm[];
    char*  Ps  = sm;                        /* 4 x 64 x 400B ring (Qs overlays slot 0) */
    float* sqp = (float*)(sm + 102400);     /* 4-slot ring x 64  = 1024B  */
    float* sqq = (float*)(sm + 103424);     /* 32 floats                  */

    const int tid  = threadIdx.x;
    const int lane = tid & 31, w = tid >> 5;
    const int mwarp = w & 1, nwarp = w >> 1;     /* 2 x 4 */
    const int mbase = mwarp * 16;
    const int qbase = blockIdx.x * 32;
    const int bb    = blockIdx.y;
    const int half  = blockIdx.z;
    const int t0    = half * 32;                 /* global tile offset */
    const char*  g3b = (const char*)(g3 + (size_t)bb * NPTS * 192);
    const float* sqb = sqg + bb * NPTS;

    /* stage queries into ring slot 0 area (transient): 32 rows x 384B */
    for (int f = tid; f < 768; f += 256) {
        int r = f / 24, c = f % 24;
        *(uint4*)(Ps + r * 400 + c * 16) =
            *(const uint4*)(g3b + (size_t)(qbase + r) * 384 + c * 16);
    }
    if (tid < 32) sqq[tid] = sqb[qbase + tid];
    __syncthreads();

    /* per-lane ldmatrix addresses */
    const unsigned Ps32 = (unsigned)__cvta_generic_to_shared(Ps);
    const int aRow = mbase + ((lane >> 3) & 1) * 8 + (lane & 7);
    const unsigned aAddr = Ps32 + aRow * 400 + ((lane >> 4) & 1) * 16;
    const int bRow = ((lane >> 4) & 1) * 8 + (lane & 7);
    const unsigned bOff = (unsigned)((nwarp * 16 + bRow) * 400 + ((lane >> 3) & 1) * 16);

    /* hoist A fragments: 3 splits x 4 k-steps, tile-invariant */
    unsigned afr[3][4][4];
#pragma unroll
    for (int pa = 0; pa < 3; pa++)
#pragma unroll
        for (int ks = 0; ks < 4; ks++)
            ldsm4(afr[pa][ks][0], afr[pa][ks][1], afr[pa][ks][2], afr[pa][ks][3],
                  aAddr + pa * 128 + ks * 32);

    const float sqiA = sqq[mbase + (lane >> 2)];
    const float sqiB = sqq[mbase + (lane >> 2) + 8];

    /* all warps done reading Qs -> ring may overwrite it */
    __syncthreads();

    /* precompute fill offsets: 6 strided (smem,gmem) pairs per thread */
    unsigned soff[6];
    unsigned goff[6];
#pragma unroll
    for (int i = 0; i < 6; i++) {
        int f = tid + i * 256;
        int r = f / 24, c = f % 24;
        soff[i] = Ps32 + (unsigned)(r * 400 + c * 16);
        goff[i] = (unsigned)(r * 384 + c * 16);
    }

    /* prologue: fill local tiles 0 and 1 into ring slots 0,1 */
#pragma unroll
    for (int p0 = 0; p0 < 2; p0++) {
        const char* src = g3b + (size_t)(t0 + p0) * 24576;
        const unsigned sbase = (unsigned)(p0 * 25600);
#pragma unroll
        for (int i = 0; i < 6; i++)
            cp_async16s(soff[i] + sbase, src + goff[i]);
        if (tid < 16) cp_async16((char*)(sqp + p0 * 64) + tid * 16,
                                 (const char*)(sqb + (t0 + p0) * 64) + tid * 16);
        cp_commit();
    }

    float tvA[5], tvB[5]; int tiA[5], tiB[5];
#pragma unroll
    for (int k = 0; k < 5; k++) {
        tvA[k] = FLT_MAX; tiA[k] = 0x7FFFFFFF;
        tvB[k] = FLT_MAX; tiB[k] = 0x7FFFFFFF;
    }

    /* FROZEN pair order (matches R6..R14 passing kernels bit-for-bit) */
    const int PA[6] = {0, 0, 1, 0, 2, 1};
    const int PB[6] = {0, 1, 0, 2, 0, 1};

    for (int tt = 0; tt < 32; tt++) {
        /* fill 2 tiles ahead into ring slot (tt+2)&3 */
        if (tt + 2 < 32) {
            const char* src = g3b + (size_t)(t0 + tt + 2) * 24576;
            const unsigned sbase = (unsigned)(((tt + 2) & 3) * 25600);
#pragma unroll
            for (int i = 0; i < 6; i++)
                cp_async16s(soff[i] + sbase, src + goff[i]);
            if (tid < 16) cp_async16((char*)(sqp + ((tt + 2) & 3) * 64) + tid * 16,
                                     (const char*)(sqb + (t0 + tt + 2) * 64) + tid * 16);
            cp_commit();
        }
        /* drain through group tt (tail-aware) */
        if (tt <= 29)      cp_wait<2>();
        else if (tt == 30) cp_wait<1>();
        else               cp_wait<0>();
        __syncthreads();    /* ONE barrier per tile */

        const unsigned bB0 = Ps32 + (tt & 3) * 25600 + bOff;
        const float* SQ = sqp + (tt & 3) * 64;

        float C[2][4];
        C[0][0]=0.f; C[0][1]=0.f; C[0][2]=0.f; C[0][3]=0.f;
        C[1][0]=0.f; C[1][1]=0.f; C[1][2]=0.f; C[1][3]=0.f;

#pragma unroll
        for (int pr = 0; pr < 6; pr++) {
            const int pa = PA[pr];
            const unsigned bB = bB0 + PB[pr] * 128;
#pragma unroll
            for (int ks = 0; ks < 4; ks++) {
                unsigned b0, b1, b2, b3;
                ldsm4(b0, b1, b2, b3, bB + ks * 32);
                mma16816(C[0], afr[pa][ks][0], afr[pa][ks][1], afr[pa][ks][2], afr[pa][ks][3], b0, b1);
                mma16816(C[1], afr[pa][ks][0], afr[pa][ks][1], afr[pa][ks][2], afr[pa][ks][3], b2, b3);
            }
        }

        /* epilogue: 8 dots per lane -> distances -> top-5 insert */
#pragma unroll
        for (int nb = 0; nb < 2; nb++) {
            const int col0 = nwarp * 16 + nb * 8 + (lane & 3) * 2;
            const float sp0 = SQ[col0], sp1 = SQ[col0 + 1];
            const int id0 = (t0 + tt) * 64 + col0;
            float d00 = fmaxf(fmaf(-2.f, C[nb][0], sqiA + sp0), 0.f);
            float d01 = fmaxf(fmaf(-2.f, C[nb][1], sqiA + sp1), 0.f);
            float d10 = fmaxf(fmaf(-2.f, C[nb][2], sqiB + sp0), 0.f);
            float d11 = fmaxf(fmaf(-2.f, C[nb][3], sqiB + sp1), 0.f);
#define INS(TV, TI, DV, IDX)                                                   \
            if (DV < TV[4]) {                                                  \
                TV[4] = DV; TI[4] = IDX;                                       \
                _Pragma("unroll")                                              \
                for (int s2 = 4; s2 > 0; s2--) {                               \
                    if (TV[s2] < TV[s2-1]) {                                   \
                        float fv = TV[s2]; TV[s2] = TV[s2-1]; TV[s2-1] = fv;   \
                        int  iv = TI[s2]; TI[s2] = TI[s2-1]; TI[s2-1] = iv;    \
                    }                                                          \
                }                                                              \
            }
            INS(tvA, tiA, d00, id0)
            INS(tvA, tiA, d01, id0 + 1)
            INS(tvB, tiB, d10, id0)
            INS(tvB, tiB, d11, id0 + 1)
#undef INS
        }
    }

    /* block merge: per query 16 lanes x 5 candidates; stride 81 */
    __syncthreads();
    float* cv = (float*)sm;
    int*   ci = (int*)(sm + 32 * 81 * 4);
    {
        const int slot = nwarp * 20 + (lane & 3) * 5;
        const int qA = mbase + (lane >> 2);
#pragma unroll
        for (int k = 0; k < 5; k++) {
            cv[qA * 81 + slot + k] = tvA[k];
            ci[qA * 81 + slot + k] = tiA[k];
            cv[(qA + 8) * 81 + slot + k] = tvB[k];
            ci[(qA + 8) * 81 + slot + k] = tiB[k];
        }
    }
    __syncthreads();
    if (tid < 32) {
        float bv[5]; int bi[5];
#pragma unroll
        for (int k = 0; k < 5; k++) { bv[k] = FLT_MAX; bi[k] = 0x7FFFFFFF; }
        for (int e = 0; e < 80; e++) {
            float v = cv[tid * 81 + e];
            int   i = ci[tid * 81 + e];
            if (v < bv[4] || (v == bv[4] && i < bi[4])) {
                bv[4] = v; bi[4] = i;
#pragma unroll
                for (int s2 = 4; s2 > 0; s2--) {
                    if (bv[s2] < bv[s2-1] || (bv[s2] == bv[s2-1] && bi[s2] < bi[s2-1])) {
                        float fv = bv[s2]; bv[s2] = bv[s2-1]; bv[s2-1] = fv;
                        int  iv = bi[s2]; bi[s2] = bi[s2-1]; bi[s2-1] = iv;
                    }
                }
            }
        }
        int base = ((bb * NPTS + qbase + tid) * 2 + half) * 5;
#pragma unroll
        for (int k = 0; k < 5; k++) { pvg[base + k] = bv[k]; pig[base + k] = bi[k]; }
    }
}

/* ---------------- KNN pass 2: merge the 2 halves -> idxflat -------------- */
__global__ void knn_merge2_kernel(const float* __restrict__ pvg, const int* __restrict__ pig,
                                  int* __restrict__ idxflat)
{
    int gid = blockIdx.x * 256 + threadIdx.x;
    if (gid >= NB * NPTS) return;
    int bb = gid >> 12;
    int q  = gid & (NPTS - 1);
    float bv[5]; int bi[5];
#pragma unroll
    for (int k = 0; k < 5; k++) { bv[k] = FLT_MAX; bi[k] = 0x7FFFFFFF; }
    const float* v = pvg + gid * 10;
    const int*   ii = pig + gid * 10;
    for (int e = 0; e < 10; e++) {
        float vv = v[e];
        int   i  = ii[e];
        if (vv < bv[4] || (vv == bv[4] && i < bi[4])) {
            bv[4] = vv; bi[4] = i;
#pragma unroll
            for (int s2 = 4; s2 > 0; s2--) {
                if (bv[s2] < bv[s2-1] || (bv[s2] == bv[s2-1] && bi[s2] < bi[s2-1])) {
                    float fv = bv[s2]; bv[s2] = bv[s2-1]; bv[s2-1] = fv;
                    int  iv = bi[s2]; bi[s2] = bi[s2-1]; bi[s2-1] = iv;
                }
            }
        }
    }
#pragma unroll
    for (int k = 0; k < 5; k++)
        idxflat[bb * NKB + k * NPTS + q] = bi[k];
}

/* ---------------- logprobs: lp[b,i,kk,layer] ----------------------------- */
__global__ void lp_kernel(const float* __restrict__ ge, const int* __restrict__ idxflat,
                          const float* __restrict__ tptr, float* __restrict__ outp, int layer)
{
    int gid = blockIdx.x * blockDim.x + threadIdx.x;
    if (gid >= NB * NKB) return;
    int bb = gid / NKB;
    int m  = gid - bb * NKB;
    float tval = fminf(fmaxf(tptr[0], -5.0f), 5.0f);
    float t = expf(tval);
    int nb  = idxflat[bb * NKB + m];
    int ctr = m / KK;
    int kk  = m - ctr * KK;
    const float4* pa = (const float4*)(ge + (bb * NPTS + nb) * DD);
    const float4* pb = (const float4*)(ge + (bb * NPTS + ctr) * DD);
    float s = 0.f;
#pragma unroll
    for (int d4 = 0; d4 < 16; d4++) {
        float4 a = pa[d4], b4 = pb[d4];
        float dx=a.x-b4.x, dy=a.y-b4.y, dz=a.z-b4.z, dw=a.w-b4.w;
        s += dx*dx + dy*dy + dz*dz + dw*dw;
    }
    outp[((bb * NPTS + ctr) * KK + kk) * 2 + layer] = -s * t;
}

/* ---------------- scatter-max edge conv --------------------------------- */
__global__ void init_acc_kernel(unsigned* __restrict__ acc) {
    int i = blockIdx.x * blockDim.x + threadIdx.x;
    if (i < NN * DD) acc[i] = NEG_MAX_KEY;
}

__global__ void scatter_kernel(const int* __restrict__ idxflat,
                               const float* __restrict__ A, const float* __restrict__ B,
                               unsigned* __restrict__ acc)
{
    int gid = blockIdx.x * blockDim.x + threadIdx.x;
    if (gid >= EDGES * 16) return;
    int q  = gid >> 4;
    int cg = gid & 15;
    int mq = q >> 2;
    int bb = (q >> 1) & 1;
    int c  = q & 1;
    int m_s = mq;
    int m_d = mq + NKB / 2;
    int srcv = (c == 0) ? idxflat[bb * NKB + m_s] : (m_s / KK);
    int dstv = (c == 0) ? idxflat[bb * NKB + m_d] : (m_d / KK);
    srcv += bb * NPTS;
    dstv += bb * NPTS;
    float4 av = ((const float4*)A)[dstv * 16 + cg];
    float4 bv = ((const float4*)B)[srcv * 16 + cg];
    unsigned* base = acc + dstv * DD + cg * 4;
    atomicMax(base + 0, fkey(av.x + bv.x));
    atomicMax(base + 1, fkey(av.y + bv.y));
    atomicMax(base + 2, fkey(av.z + bv.z));
    atomicMax(base + 3, fkey(av.w + bv.w));
}

/* decode + relu; also re-initializes acc for the next layer (saves launch) */
__global__ void decode_relu_kernel(unsigned* __restrict__ acc, float* __restrict__ y) {
    int i = blockIdx.x * blockDim.x + threadIdx.x;
    if (i < NN * DD) {
        unsigned u = acc[i];
        y[i] = fmaxf(fdec(u), 0.0f);
        acc[i] = NEG_MAX_KEY;
    }
}

/* ------- fused head: decode(acc) -> lrelu(x@Wf1+b)@Wf2+b (no x3 pass) --- */
__global__ __launch_bounds__(128) void head_kernel(
    const unsigned* __restrict__ acc,
    const float* __restrict__ Wf1, const float* __restrict__ bf1,
    const float* __restrict__ Wf2, const float* __restrict__ bf2,
    float* __restrict__ out)
{
    __shared__ float w1[64 * 32];
    __shared__ float w2[32 * 8];
    __shared__ float b1s[32], b2s[8];
    int t = threadIdx.x;
    for (int f = t; f < 2048; f += 128) w1[f] = Wf1[f];
    for (int f = t; f < 256;  f += 128) w2[f] = Wf2[f];
    if (t < 32) b1s[t] = bf1[t];
    if (t < 8)  b2s[t] = bf2[t];
    __syncthreads();
    int r = blockIdx.x * 128 + t;
    if (r >= NN) return;
    float xr[64];
#pragma unroll
    for (int d4 = 0; d4 < 16; d4++) {
        uint4 v = ((const uint4*)(acc + r * DD))[d4];
        xr[d4*4+0] = fmaxf(fdec(v.x), 0.0f);
        xr[d4*4+1] = fmaxf(fdec(v.y), 0.0f);
        xr[d4*4+2] = fmaxf(fdec(v.z), 0.0f);
        xr[d4*4+3] = fmaxf(fdec(v.w), 0.0f);
    }
    float o[8];
#pragma unroll
    for (int k = 0; k < 8; k++) o[k] = b2s[k];
    for (int jj = 0; jj < 32; jj++) {
        float h0=0.f,h1=0.f,h2=0.f,h3=0.f;
#pragma unroll
        for (int k = 0; k < 64; k += 4) {
            h0 += xr[k+0] * w1[(k+0)*32 + jj];
            h1 += xr[k+1] * w1[(k+1)*32 + jj];
            h2 += xr[k+2] * w1[(k+2)*32 + jj];
            h3 += xr[k+3] * w1[(k+3)*32 + jj];
        }
        float h = ((h0+h1)+(h2+h3)) + b1s[jj];
        h = h > 0.f ? h : 0.1f * h;
#pragma unroll
        for (int k = 0; k < 8; k++) o[k] += h * w2[jj*8 + k];
    }
#pragma unroll
    for (int k = 0; k < 8; k++) out[r * 8 + k] = o[k];
}

/* ---------------- launch ------------------------------------------------- */
extern "C" void kernel_launch(void* const* d_in, const int* in_sizes, int n_in,
                              void* d_out, int out_size)
{
    const float* x     = (const float*)d_in[0];
    const float* W_pre = (const float*)d_in[1];
    const float* b_pre = (const float*)d_in[2];
    const float* W_d1  = (const float*)d_in[3];
    const float* b_d1  = (const float*)d_in[4];
    const float* t1    = (const float*)d_in[5];
    const float* W_c1  = (const float*)d_in[6];
    const float* b_c1  = (const float*)d_in[7];
    const float* W_d2  = (const float*)d_in[8];
    const float* b_d2  = (const float*)d_in[9];
    const float* t2    = (const float*)d_in[10];
    const float* W_c2  = (const float*)d_in[11];
    const float* b_c2  = (const float*)d_in[12];
    const float* W_f1  = (const float*)d_in[13];
    const float* b_f1  = (const float*)d_in[14];
    const float* W_f2  = (const float*)d_in[15];
    const float* b_f2  = (const float*)d_in[16];

    float* out = (float*)d_out;            /* [2,4096,8] = 65536 floats   */
    float* lp  = out + NN * 8;             /* [2,4096,5,2] = 81920 floats */

    float *p_xf1, *p_ge1, *p_ge2, *p_sq, *p_A, *p_B, *p_x2, *p_pv;
    int *p_idx1, *p_idx2, *p_pi;
    unsigned *p_acc;
    __nv_bfloat16 *p_g3;
    cudaGetSymbolAddress((void**)&p_xf1,  g_xf1);
    cudaGetSymbolAddress((void**)&p_ge1,  g_ge1);
    cudaGetSymbolAddress((void**)&p_ge2,  g_ge2);
    cudaGetSymbolAddress((void**)&p_sq,   g_sq);
    cudaGetSymbolAddress((void**)&p_idx1, g_idx1);
    cudaGetSymbolAddress((void**)&p_idx2, g_idx2);
    cudaGetSymbolAddress((void**)&p_A,    g_A);
    cudaGetSymbolAddress((void**)&p_B,    g_B);
    cudaGetSymbolAddress((void**)&p_acc,  g_acc);
    cudaGetSymbolAddress((void**)&p_x2,   g_x2);
    cudaGetSymbolAddress((void**)&p_g3,   g_g3);
    cudaGetSymbolAddress((void**)&p_pv,   g_pv);
    cudaGetSymbolAddress((void**)&p_pi,   g_pi);

    cudaFuncSetAttribute(knn_mma_kernel, cudaFuncAttributeMaxDynamicSharedMemorySize, KNN_SMEM);

    const float* nul = nullptr;
    dim3 knn_grid(NPTS / 32, NB, 2);

    /* pre MLP + embed 1 */
    gemm_act<64><<<NN/64, 256>>>(x,     32, nul, 0, W_pre, b_pre, p_xf1, 1);
    gemm_act<64><<<NN/64, 256>>>(p_xf1, 64, nul, 0, W_d1,  b_d1,  p_ge1, 0);

    /* knn 1 + lp 1 */
    prep3_kernel<<<(NN*DD)/256, 256>>>(p_ge1, p_g3, p_sq);
    knn_mma_kernel<<<knn_grid, 256, KNN_SMEM>>>(p_g3, p_sq, p_pv, p_pi);
    knn_merge2_kernel<<<(NB*NPTS)/256, 256>>>(p_pv, p_pi, p_idx1);
    lp_kernel<<<(NB*NKB)/256, 256>>>(p_ge1, p_idx1, t1, lp, 0);

    /* edge conv 1 */
    gemm_ab<<<NN/64, 256>>>(p_xf1, W_c1, b_c1, p_A, p_B);
    init_acc_kernel<<<(NN*DD)/256, 256>>>(p_acc);
    scatter_kernel<<<(EDGES*16)/256, 256>>>(p_idx1, p_A, p_B, p_acc);
    decode_relu_kernel<<<(NN*DD)/256, 256>>>(p_acc, p_x2);

    /* embed 2 on concat[ge1, x2] */
    gemm_act<64><<<NN/64, 256>>>(p_ge1, 64, p_x2, 64, W_d2, b_d2, p_ge2, 0);

    /* knn 2 + lp 2 */
    prep3_kernel<<<(NN*DD)/256, 256>>>(p_ge2, p_g3, p_sq);
    knn_mma_kernel<<<knn_grid, 256, KNN_SMEM>>>(p_g3, p_sq, p_pv, p_pi);
    knn_merge2_kernel<<<(NB*NPTS)/256, 256>>>(p_pv, p_pi, p_idx2);
    lp_kernel<<<(NB*NKB)/256, 256>>>(p_ge2, p_idx2, t2, lp, 1);

    /* edge conv 2 (acc already re-initialized by decode_relu of layer 1) */
    gemm_ab<<<NN/64, 256>>>(p_x2, W_c2, b_c2, p_A, p_B);
    scatter_kernel<<<(EDGES*16)/256, 256>>>(p_idx2, p_A, p_B, p_acc);

    /* head (decode fused) */
    head_kernel<<<NN/128, 128>>>(p_acc, W_f1, b_f1, W_f2, b_f2, out);
}

// round 17
// speedup vs baseline: 1.4909x; 1.1418x over previous
#include <cuda_runtime.h>
#include <cuda_bf16.h>
#include <float.h>
#include <math.h>

#define NPTS 4096
#define NB 2
#define NN 8192
#define DD 64
#define KK 5
#define NKB (NPTS*KK)      /* 20480 flat (k-major) per batch */
#define EDGES (NB*NKB)     /* 40960 edges */

/* ---------------- scratch (device globals; no allocation allowed) -------- */
__device__ float         g_xf1[NN*DD];
__device__ float         g_ge1[NN*DD];
__device__ float         g_ge2[NN*DD];
__device__ float         g_sq [NN];
__device__ int           g_idx1[NB*NKB];
__device__ int           g_idx2[NB*NKB];
__device__ float         g_A  [NN*DD];
__device__ float         g_B  [NN*DD];
__device__ unsigned      g_acc[NN*DD];
__device__ float         g_x2 [NN*DD];
__device__ __nv_bfloat16 g_g3 [NN*192];   /* 3-way bf16 split of embeddings */

/* ordered float<->uint key (monotone map, finite floats) */
__device__ __forceinline__ unsigned fkey(float f) {
    unsigned u = __float_as_uint(f);
    return u ^ ((unsigned)(((int)u) >> 31) | 0x80000000u);
}
__device__ __forceinline__ float fdec(unsigned u) {
    unsigned v = u ^ ((u & 0x80000000u) ? 0x80000000u : 0xFFFFFFFFu);
    return __uint_as_float(v);
}
#define NEG_MAX_KEY 0x00800000u   /* fkey(-FLT_MAX) */

/* cp.async helpers */
__device__ __forceinline__ void cp_async16(void* smem_dst, const void* gsrc) {
    unsigned s = (unsigned)__cvta_generic_to_shared(smem_dst);
    asm volatile("cp.async.ca.shared.global [%0], [%1], 16;" :: "r"(s), "l"(gsrc));
}
__device__ __forceinline__ void cp_async16s(unsigned smem_addr, const void* gsrc) {
    asm volatile("cp.async.ca.shared.global [%0], [%1], 16;" :: "r"(smem_addr), "l"(gsrc));
}
__device__ __forceinline__ void cp_commit() {
    asm volatile("cp.async.commit_group;" ::: "memory");
}
template<int N> __device__ __forceinline__ void cp_wait() {
    asm volatile("cp.async.wait_group %0;" :: "n"(N) : "memory");
}

/* ldmatrix x4 (b16), shared address precomputed by caller */
__device__ __forceinline__ void ldsm4(unsigned &r0, unsigned &r1, unsigned &r2, unsigned &r3,
                                      unsigned saddr) {
    asm volatile("ldmatrix.sync.aligned.m8n8.x4.shared.b16 {%0,%1,%2,%3}, [%4];"
                 : "=r"(r0), "=r"(r1), "=r"(r2), "=r"(r3) : "r"(saddr));
}

/* mma m16n8k16 row.col f32 <- bf16 x bf16 + f32 */
__device__ __forceinline__ void mma16816(float* c, unsigned a0, unsigned a1,
                                         unsigned a2, unsigned a3,
                                         unsigned b0, unsigned b1) {
    asm volatile("mma.sync.aligned.m16n8k16.row.col.f32.bf16.bf16.f32 "
                 "{%0,%1,%2,%3}, {%4,%5,%6,%7}, {%8,%9}, {%0,%1,%2,%3};"
                 : "+f"(c[0]), "+f"(c[1]), "+f"(c[2]), "+f"(c[3])
                 : "r"(a0), "r"(a1), "r"(a2), "r"(a3), "r"(b0), "r"(b1));
}

/* ---------------- generic small GEMM: Y = act(X@W + b), 64 rows/block ---- */
template<int NCOL>
__global__ __launch_bounds__(256) void gemm_act(
    const float* __restrict__ X1, int k1,
    const float* __restrict__ X2, int k2,
    const float* __restrict__ W, const float* __restrict__ bias,
    float* __restrict__ Y, int act)
{
    constexpr int G  = NCOL / 4;
    constexpr int TY = 256 / G;
    constexpr int R  = 64 / TY;
    __shared__ float Ws[128 * NCOL];
    __shared__ float Xs[64 * 33];
    __shared__ float bs[NCOL];
    const int t = threadIdx.x;
    const int rowBase = blockIdx.x * 64;
    const int KD = k1 + k2;

    for (int f = t; f < KD * NCOL; f += 256) Ws[f] = W[f];
    if (t < NCOL) bs[t] = (bias != nullptr) ? bias[t] : 0.0f;

    const int tx = t % G, ty = t / G;
    float acc[R][4];
#pragma unroll
    for (int rr = 0; rr < R; rr++) { acc[rr][0]=0.f; acc[rr][1]=0.f; acc[rr][2]=0.f; acc[rr][3]=0.f; }

    for (int ko = 0; ko < KD; ko += 32) {
        const float* Xsrc; int stride, koff;
        if (ko < k1) { Xsrc = X1; stride = k1; koff = ko; }
        else         { Xsrc = X2; stride = k2; koff = ko - k1; }
        __syncthreads();
        for (int f = t; f < 64 * 32; f += 256) {
            int r = f >> 5, k = f & 31;
            Xs[r * 33 + k] = Xsrc[(rowBase + r) * stride + koff + k];
        }
        __syncthreads();
#pragma unroll
        for (int k = 0; k < 32; k++) {
            float4 w4 = *(const float4*)(Ws + (ko + k) * NCOL + tx * 4);
#pragma unroll
            for (int rr = 0; rr < R; rr++) {
                float xv = Xs[(ty + rr * TY) * 33 + k];
                acc[rr][0] += xv * w4.x; acc[rr][1] += xv * w4.y;
                acc[rr][2] += xv * w4.z; acc[rr][3] += xv * w4.w;
            }
        }
    }
#pragma unroll
    for (int rr = 0; rr < R; rr++) {
        int r = rowBase + ty + rr * TY;
        float4 o;
        o.x = acc[rr][0] + bs[tx*4+0];
        o.y = acc[rr][1] + bs[tx*4+1];
        o.z = acc[rr][2] + bs[tx*4+2];
        o.w = acc[rr][3] + bs[tx*4+3];
        if (act == 1) {          /* leaky relu 0.1 */
            o.x = o.x > 0.f ? o.x : 0.1f*o.x; o.y = o.y > 0.f ? o.y : 0.1f*o.y;
            o.z = o.z > 0.f ? o.z : 0.1f*o.z; o.w = o.w > 0.f ? o.w : 0.1f*o.w;
        } else if (act == 2) {   /* relu */
            o.x = fmaxf(o.x,0.f); o.y = fmaxf(o.y,0.f);
            o.z = fmaxf(o.z,0.f); o.w = fmaxf(o.w,0.f);
        }
        *(float4*)(Y + r * NCOL + tx * 4) = o;
    }
}

/* -- fused EdgeConv GEMMs (+ optional acc init in extra blocks):
      A = X@(Wtop-Wbot)+bias, B = X@Wbot; blocks >=128 init acc ---------- */
__global__ __launch_bounds__(256) void gemm_ab(
    const float* __restrict__ X, const float* __restrict__ Wc,
    const float* __restrict__ bias, float* __restrict__ A, float* __restrict__ B,
    unsigned* __restrict__ accInit)
{
    if (blockIdx.x >= 128) {
        /* init region: 64 blocks x 256 threads x 8 uint4 = 524288 words */
        unsigned base = ((blockIdx.x - 128) * 256 + threadIdx.x) * 4;
        uint4 v = make_uint4(NEG_MAX_KEY, NEG_MAX_KEY, NEG_MAX_KEY, NEG_MAX_KEY);
#pragma unroll
        for (int i = 0; i < 8; i++)
            *(uint4*)(accInit + base + (unsigned)i * 65536u) = v;
        return;
    }
    __shared__ float Ws[128 * 64];
    __shared__ float Xs[64 * 33];
    __shared__ float bs[64];
    const int t = threadIdx.x;
    const int rowBase = blockIdx.x * 64;
    for (int f = t; f < 128 * 64; f += 256) Ws[f] = Wc[f];
    if (t < 64) bs[t] = bias[t];

    const int tx = t % 16, ty = t / 16;        /* 16 col-groups x 16 rows */
    float aT[4][4], aB[4][4];
#pragma unroll
    for (int rr = 0; rr < 4; rr++)
#pragma unroll
        for (int c = 0; c < 4; c++) { aT[rr][c] = 0.f; aB[rr][c] = 0.f; }

    for (int ko = 0; ko < 64; ko += 32) {
        __syncthreads();
        for (int f = t; f < 64 * 32; f += 256) {
            int r = f >> 5, k = f & 31;
            Xs[r * 33 + k] = X[(rowBase + r) * 64 + ko + k];
        }
        __syncthreads();
#pragma unroll
        for (int k = 0; k < 32; k++) {
            float4 wt = *(const float4*)(Ws + (ko + k) * 64 + tx * 4);
            float4 wb = *(const float4*)(Ws + (64 + ko + k) * 64 + tx * 4);
#pragma unroll
            for (int rr = 0; rr < 4; rr++) {
                float xv = Xs[(ty + rr * 16) * 33 + k];
                aT[rr][0] = fmaf(xv, wt.x, aT[rr][0]); aT[rr][1] = fmaf(xv, wt.y, aT[rr][1]);
                aT[rr][2] = fmaf(xv, wt.z, aT[rr][2]); aT[rr][3] = fmaf(xv, wt.w, aT[rr][3]);
                aB[rr][0] = fmaf(xv, wb.x, aB[rr][0]); aB[rr][1] = fmaf(xv, wb.y, aB[rr][1]);
                aB[rr][2] = fmaf(xv, wb.z, aB[rr][2]); aB[rr][3] = fmaf(xv, wb.w, aB[rr][3]);
            }
        }
    }
#pragma unroll
    for (int rr = 0; rr < 4; rr++) {
        int r = rowBase + ty + rr * 16;
        float4 ao, bo;
        ao.x = aT[rr][0] - aB[rr][0] + bs[tx*4+0];
        ao.y = aT[rr][1] - aB[rr][1] + bs[tx*4+1];
        ao.z = aT[rr][2] - aB[rr][2] + bs[tx*4+2];
        ao.w = aT[rr][3] - aB[rr][3] + bs[tx*4+3];
        bo.x = aB[rr][0]; bo.y = aB[rr][1]; bo.z = aB[rr][2]; bo.w = aB[rr][3];
        *(float4*)(A + r * 64 + tx * 4) = ao;
        *(float4*)(B + r * 64 + tx * 4) = bo;
    }
}

/* -------- prep: sum of squares + 3-way bf16 split (FROZEN arithmetic) ---- */
__global__ void prep3_kernel(const float* __restrict__ ge,
                             __nv_bfloat16* __restrict__ g3,
                             float* __restrict__ sq)
{
    int i = blockIdx.x * 256 + threadIdx.x;
    if (i >= NN * DD) return;
    int r = i >> 6, d = i & 63;
    float v = ge[i];
    __nv_bfloat16 b0 = __float2bfloat16_rn(v);
    float r1 = v - __bfloat162float(b0);
    __nv_bfloat16 b1 = __float2bfloat16_rn(r1);
    float r2 = r1 - __bfloat162float(b1);
    __nv_bfloat16 b2 = __float2bfloat16_rn(r2);
    __nv_bfloat16* row = g3 + (size_t)r * 192;
    row[d] = b0; row[64 + d] = b1; row[128 + d] = b2;

    if (d == 0) {   /* one thread per row does the sq reduction */
        const float4* p = (const float4*)(ge + r * DD);
        float s0=0.f,s1=0.f,s2=0.f,s3=0.f;
#pragma unroll
        for (int d4 = 0; d4 < 16; d4++) {
            float4 w = p[d4];
            s0 += w.x*w.x; s1 += w.y*w.y; s2 += w.z*w.z; s3 += w.w*w.w;
        }
        sq[r] = (s0+s1)+(s2+s3);
    }
}

/* ---------------- KNN via bf16-split tensor-core GEMM (R14 verbatim) -----
   CTA: 32 queries x all 4096 points; 8 warps = 2 m-warps x 4 n-warps;
   256 threads, OCCUPANCY 2. 4-deep Ps ring, distance-2 prefetch, ONE
   barrier per tile, strength-reduced fill addressing.
   Per-element accumulation order BIT-IDENTICAL to R6..R14 passing kernels
   (frozen PA/PB/ks order, same HMMA); ascending-index scan + (val,idx)-lex
   merge are partition-invariant -> selection provably identical.          */
#define KNN_SMEM 103680
__global__ __launch_bounds__(256, 2) void knn_mma_kernel(
    const __nv_bfloat16* __restrict__ g3, const float* __restrict__ sqg,
    int* __restrict__ idxflat)
{
    extern __shared__ char sm[];
    char*  Ps  = sm;                        /* 4 x 64 x 400B ring (Qs overlays slot 0) */
    float* sqp = (float*)(sm + 102400);     /* 4-slot ring x 64  = 1024B  */
    float* sqq = (float*)(sm + 103424);     /* 32 floats                  */

    const int tid  = threadIdx.x;
    const int lane = tid & 31, w = tid >> 5;
    const int mwarp = w & 1, nwarp = w >> 1;     /* 2 x 4 */
    const int mbase = mwarp * 16;
    const int qbase = blockIdx.x * 32;
    const int bb    = blockIdx.y;
    const char*  g3b = (const char*)(g3 + (size_t)bb * NPTS * 192);
    const float* sqb = sqg + bb * NPTS;

    /* stage queries into ring slot 0 area (transient): 32 rows x 384B */
    for (int f = tid; f < 768; f += 256) {
        int r = f / 24, c = f % 24;
        *(uint4*)(Ps + r * 400 + c * 16) =
            *(const uint4*)(g3b + (size_t)(qbase + r) * 384 + c * 16);
    }
    if (tid < 32) sqq[tid] = sqb[qbase + tid];
    __syncthreads();

    /* per-lane ldmatrix addresses */
    const unsigned Ps32 = (unsigned)__cvta_generic_to_shared(Ps);
    const int aRow = mbase + ((lane >> 3) & 1) * 8 + (lane & 7);
    const unsigned aAddr = Ps32 + aRow * 400 + ((lane >> 4) & 1) * 16;
    const int bRow = ((lane >> 4) & 1) * 8 + (lane & 7);
    const unsigned bOff = (unsigned)((nwarp * 16 + bRow) * 400 + ((lane >> 3) & 1) * 16);

    /* hoist A fragments: 3 splits x 4 k-steps, tile-invariant */
    unsigned afr[3][4][4];
#pragma unroll
    for (int pa = 0; pa < 3; pa++)
#pragma unroll
        for (int ks = 0; ks < 4; ks++)
            ldsm4(afr[pa][ks][0], afr[pa][ks][1], afr[pa][ks][2], afr[pa][ks][3],
                  aAddr + pa * 128 + ks * 32);

    const float sqiA = sqq[mbase + (lane >> 2)];
    const float sqiB = sqq[mbase + (lane >> 2) + 8];

    /* all warps done reading Qs -> ring may overwrite it */
    __syncthreads();

    /* precompute fill offsets: 6 strided (smem,gmem) pairs per thread */
    unsigned soff[6];
    unsigned goff[6];
#pragma unroll
    for (int i = 0; i < 6; i++) {
        int f = tid + i * 256;
        int r = f / 24, c = f % 24;
        soff[i] = Ps32 + (unsigned)(r * 400 + c * 16);
        goff[i] = (unsigned)(r * 384 + c * 16);
    }

    /* prologue: fill tiles 0 and 1 into ring slots 0,1 */
#pragma unroll
    for (int p0 = 0; p0 < 2; p0++) {
        const char* src = g3b + (size_t)p0 * 24576;
        const unsigned sbase = (unsigned)(p0 * 25600);
#pragma unroll
        for (int i = 0; i < 6; i++)
            cp_async16s(soff[i] + sbase, src + goff[i]);
        if (tid < 16) cp_async16((char*)(sqp + p0 * 64) + tid * 16,
                                 (const char*)(sqb + p0 * 64) + tid * 16);
        cp_commit();
    }

    float tvA[5], tvB[5]; int tiA[5], tiB[5];
#pragma unroll
    for (int k = 0; k < 5; k++) {
        tvA[k] = FLT_MAX; tiA[k] = 0x7FFFFFFF;
        tvB[k] = FLT_MAX; tiB[k] = 0x7FFFFFFF;
    }

    /* FROZEN pair order (matches R6..R14 passing kernels bit-for-bit) */
    const int PA[6] = {0, 0, 1, 0, 2, 1};
    const int PB[6] = {0, 1, 0, 2, 0, 1};

    for (int tt = 0; tt < 64; tt++) {
        /* fill 2 tiles ahead into ring slot (tt+2)&3 */
        if (tt + 2 < 64) {
            const char* src = g3b + (size_t)(tt + 2) * 24576;
            const unsigned sbase = (unsigned)(((tt + 2) & 3) * 25600);
#pragma unroll
            for (int i = 0; i < 6; i++)
                cp_async16s(soff[i] + sbase, src + goff[i]);
            if (tid < 16) cp_async16((char*)(sqp + ((tt + 2) & 3) * 64) + tid * 16,
                                     (const char*)(sqb + (tt + 2) * 64) + tid * 16);
            cp_commit();
        }
        /* drain through group tt (tail-aware) */
        if (tt <= 61)      cp_wait<2>();
        else if (tt == 62) cp_wait<1>();
        else               cp_wait<0>();
        __syncthreads();    /* ONE barrier per tile */

        const unsigned bB0 = Ps32 + (tt & 3) * 25600 + bOff;
        const float* SQ = sqp + (tt & 3) * 64;

        float C[2][4];
        C[0][0]=0.f; C[0][1]=0.f; C[0][2]=0.f; C[0][3]=0.f;
        C[1][0]=0.f; C[1][1]=0.f; C[1][2]=0.f; C[1][3]=0.f;

#pragma unroll
        for (int pr = 0; pr < 6; pr++) {
            const int pa = PA[pr];
            const unsigned bB = bB0 + PB[pr] * 128;
#pragma unroll
            for (int ks = 0; ks < 4; ks++) {
                unsigned b0, b1, b2, b3;
                ldsm4(b0, b1, b2, b3, bB + ks * 32);
                mma16816(C[0], afr[pa][ks][0], afr[pa][ks][1], afr[pa][ks][2], afr[pa][ks][3], b0, b1);
                mma16816(C[1], afr[pa][ks][0], afr[pa][ks][1], afr[pa][ks][2], afr[pa][ks][3], b2, b3);
            }
        }

        /* epilogue: 8 dots per lane -> distances -> top-5 insert */
#pragma unroll
        for (int nb = 0; nb < 2; nb++) {
            const int col0 = nwarp * 16 + nb * 8 + (lane & 3) * 2;
            const float sp0 = SQ[col0], sp1 = SQ[col0 + 1];
            const int id0 = tt * 64 + col0;
            float d00 = fmaxf(fmaf(-2.f, C[nb][0], sqiA + sp0), 0.f);
            float d01 = fmaxf(fmaf(-2.f, C[nb][1], sqiA + sp1), 0.f);
            float d10 = fmaxf(fmaf(-2.f, C[nb][2], sqiB + sp0), 0.f);
            float d11 = fmaxf(fmaf(-2.f, C[nb][3], sqiB + sp1), 0.f);
#define INS(TV, TI, DV, IDX)                                                   \
            if (DV < TV[4]) {                                                  \
                TV[4] = DV; TI[4] = IDX;                                       \
                _Pragma("unroll")                                              \
                for (int s2 = 4; s2 > 0; s2--) {                               \
                    if (TV[s2] < TV[s2-1]) {                                   \
                        float fv = TV[s2]; TV[s2] = TV[s2-1]; TV[s2-1] = fv;   \
                        int  iv = TI[s2]; TI[s2] = TI[s2-1]; TI[s2-1] = iv;    \
                    }                                                          \
                }                                                              \
            }
            INS(tvA, tiA, d00, id0)
            INS(tvA, tiA, d01, id0 + 1)
            INS(tvB, tiB, d10, id0)
            INS(tvB, tiB, d11, id0 + 1)
#undef INS
        }
    }

    /* block merge: per query 16 lanes x 5 candidates; stride 81 */
    __syncthreads();
    float* cv = (float*)sm;
    int*   ci = (int*)(sm + 32 * 81 * 4);
    {
        const int slot = nwarp * 20 + (lane & 3) * 5;
        const int qA = mbase + (lane >> 2);
#pragma unroll
        for (int k = 0; k < 5; k++) {
            cv[qA * 81 + slot + k] = tvA[k];
            ci[qA * 81 + slot + k] = tiA[k];
            cv[(qA + 8) * 81 + slot + k] = tvB[k];
            ci[(qA + 8) * 81 + slot + k] = tiB[k];
        }
    }
    __syncthreads();
    if (tid < 32) {
        float bv[5]; int bi[5];
#pragma unroll
        for (int k = 0; k < 5; k++) { bv[k] = FLT_MAX; bi[k] = 0x7FFFFFFF; }
        for (int e = 0; e < 80; e++) {
            float v = cv[tid * 81 + e];
            int   i = ci[tid * 81 + e];
            if (v < bv[4] || (v == bv[4] && i < bi[4])) {
                bv[4] = v; bi[4] = i;
#pragma unroll
                for (int s2 = 4; s2 > 0; s2--) {
                    if (bv[s2] < bv[s2-1] || (bv[s2] == bv[s2-1] && bi[s2] < bi[s2-1])) {
                        float fv = bv[s2]; bv[s2] = bv[s2-1]; bv[s2-1] = fv;
                        int  iv = bi[s2]; bi[s2] = bi[s2-1]; bi[s2-1] = iv;
                    }
                }
            }
        }
#pragma unroll
        for (int k = 0; k < 5; k++)
            idxflat[bb * NKB + k * NPTS + qbase + tid] = bi[k];
    }
}

/* -------- fused lp + scatter: blocks [0,160) lp, [160,2720) scatter ------ */
__global__ void lp_scatter_kernel(
    const float* __restrict__ ge, const int* __restrict__ idxflat,
    const float* __restrict__ tptr, float* __restrict__ outp, int layer,
    const float* __restrict__ A, const float* __restrict__ B,
    unsigned* __restrict__ acc)
{
    if (blockIdx.x < 160) {
        int gid = blockIdx.x * 256 + threadIdx.x;
        if (gid >= NB * NKB) return;
        int bb = gid / NKB;
        int m  = gid - bb * NKB;
        float tval = fminf(fmaxf(tptr[0], -5.0f), 5.0f);
        float t = expf(tval);
        int nb  = idxflat[bb * NKB + m];
        int ctr = m / KK;
        int kk  = m - ctr * KK;
        const float4* pa = (const float4*)(ge + (bb * NPTS + nb) * DD);
        const float4* pb = (const float4*)(ge + (bb * NPTS + ctr) * DD);
        float s = 0.f;
#pragma unroll
        for (int d4 = 0; d4 < 16; d4++) {
            float4 a = pa[d4], b4 = pb[d4];
            float dx=a.x-b4.x, dy=a.y-b4.y, dz=a.z-b4.z, dw=a.w-b4.w;
            s += dx*dx + dy*dy + dz*dz + dw*dw;
        }
        outp[((bb * NPTS + ctr) * KK + kk) * 2 + layer] = -s * t;
    } else {
        int gid = (blockIdx.x - 160) * 256 + threadIdx.x;
        if (gid >= EDGES * 16) return;
        int q  = gid >> 4;
        int cg = gid & 15;
        int mq = q >> 2;
        int bb = (q >> 1) & 1;
        int c  = q & 1;
        int m_s = mq;
        int m_d = mq + NKB / 2;
        int srcv = (c == 0) ? idxflat[bb * NKB + m_s] : (m_s / KK);
        int dstv = (c == 0) ? idxflat[bb * NKB + m_d] : (m_d / KK);
        srcv += bb * NPTS;
        dstv += bb * NPTS;
        float4 av = ((const float4*)A)[dstv * 16 + cg];
        float4 bv = ((const float4*)B)[srcv * 16 + cg];
        unsigned* base = acc + dstv * DD + cg * 4;
        atomicMax(base + 0, fkey(av.x + bv.x));
        atomicMax(base + 1, fkey(av.y + bv.y));
        atomicMax(base + 2, fkey(av.z + bv.z));
        atomicMax(base + 3, fkey(av.w + bv.w));
    }
}

/* decode + relu; also re-initializes acc for the next layer (saves launch) */
__global__ void decode_relu_kernel(unsigned* __restrict__ acc, float* __restrict__ y) {
    int i = blockIdx.x * blockDim.x + threadIdx.x;
    if (i < NN * DD) {
        unsigned u = acc[i];
        y[i] = fmaxf(fdec(u), 0.0f);
        acc[i] = NEG_MAX_KEY;
    }
}

/* ------- fused head: decode(acc) -> lrelu(x@Wf1+b)@Wf2+b (no x3 pass) --- */
__global__ __launch_bounds__(128) void head_kernel(
    const unsigned* __restrict__ acc,
    const float* __restrict__ Wf1, const float* __restrict__ bf1,
    const float* __restrict__ Wf2, const float* __restrict__ bf2,
    float* __restrict__ out)
{
    __shared__ float w1[64 * 32];
    __shared__ float w2[32 * 8];
    __shared__ float b1s[32], b2s[8];
    int t = threadIdx.x;
    for (int f = t; f < 2048; f += 128) w1[f] = Wf1[f];
    for (int f = t; f < 256;  f += 128) w2[f] = Wf2[f];
    if (t < 32) b1s[t] = bf1[t];
    if (t < 8)  b2s[t] = bf2[t];
    __syncthreads();
    int r = blockIdx.x * 128 + t;
    if (r >= NN) return;
    float xr[64];
#pragma unroll
    for (int d4 = 0; d4 < 16; d4++) {
        uint4 v = ((const uint4*)(acc + r * DD))[d4];
        xr[d4*4+0] = fmaxf(fdec(v.x), 0.0f);
        xr[d4*4+1] = fmaxf(fdec(v.y), 0.0f);
        xr[d4*4+2] = fmaxf(fdec(v.z), 0.0f);
        xr[d4*4+3] = fmaxf(fdec(v.w), 0.0f);
    }
    float o[8];
#pragma unroll
    for (int k = 0; k < 8; k++) o[k] = b2s[k];
    for (int jj = 0; jj < 32; jj++) {
        float h0=0.f,h1=0.f,h2=0.f,h3=0.f;
#pragma unroll
        for (int k = 0; k < 64; k += 4) {
            h0 += xr[k+0] * w1[(k+0)*32 + jj];
            h1 += xr[k+1] * w1[(k+1)*32 + jj];
            h2 += xr[k+2] * w1[(k+2)*32 + jj];
            h3 += xr[k+3] * w1[(k+3)*32 + jj];
        }
        float h = ((h0+h1)+(h2+h3)) + b1s[jj];
        h = h > 0.f ? h : 0.1f * h;
#pragma unroll
        for (int k = 0; k < 8; k++) o[k] += h * w2[jj*8 + k];
    }
#pragma unroll
    for (int k = 0; k < 8; k++) out[r * 8 + k] = o[k];
}

/* ---------------- launch ------------------------------------------------- */
extern "C" void kernel_launch(void* const* d_in, const int* in_sizes, int n_in,
                              void* d_out, int out_size)
{
    const float* x     = (const float*)d_in[0];
    const float* W_pre = (const float*)d_in[1];
    const float* b_pre = (const float*)d_in[2];
    const float* W_d1  = (const float*)d_in[3];
    const float* b_d1  = (const float*)d_in[4];
    const float* t1    = (const float*)d_in[5];
    const float* W_c1  = (const float*)d_in[6];
    const float* b_c1  = (const float*)d_in[7];
    const float* W_d2  = (const float*)d_in[8];
    const float* b_d2  = (const float*)d_in[9];
    const float* t2    = (const float*)d_in[10];
    const float* W_c2  = (const float*)d_in[11];
    const float* b_c2  = (const float*)d_in[12];
    const float* W_f1  = (const float*)d_in[13];
    const float* b_f1  = (const float*)d_in[14];
    const float* W_f2  = (const float*)d_in[15];
    const float* b_f2  = (const float*)d_in[16];

    float* out = (float*)d_out;            /* [2,4096,8] = 65536 floats   */
    float* lp  = out + NN * 8;             /* [2,4096,5,2] = 81920 floats */

    float *p_xf1, *p_ge1, *p_ge2, *p_sq, *p_A, *p_B, *p_x2;
    int *p_idx1, *p_idx2;
    unsigned *p_acc;
    __nv_bfloat16 *p_g3;
    cudaGetSymbolAddress((void**)&p_xf1,  g_xf1);
    cudaGetSymbolAddress((void**)&p_ge1,  g_ge1);
    cudaGetSymbolAddress((void**)&p_ge2,  g_ge2);
    cudaGetSymbolAddress((void**)&p_sq,   g_sq);
    cudaGetSymbolAddress((void**)&p_idx1, g_idx1);
    cudaGetSymbolAddress((void**)&p_idx2, g_idx2);
    cudaGetSymbolAddress((void**)&p_A,    g_A);
    cudaGetSymbolAddress((void**)&p_B,    g_B);
    cudaGetSymbolAddress((void**)&p_acc,  g_acc);
    cudaGetSymbolAddress((void**)&p_x2,   g_x2);
    cudaGetSymbolAddress((void**)&p_g3,   g_g3);

    cudaFuncSetAttribute(knn_mma_kernel, cudaFuncAttributeMaxDynamicSharedMemorySize, KNN_SMEM);

    const float* nul = nullptr;
    dim3 knn_grid(NPTS / 32, NB);

    /* pre MLP + embed 1 */
    gemm_act<64><<<NN/64, 256>>>(x,     32, nul, 0, W_pre, b_pre, p_xf1, 1);
    gemm_act<64><<<NN/64, 256>>>(p_xf1, 64, nul, 0, W_d1,  b_d1,  p_ge1, 0);

    /* prep + edge-conv GEMMs (A/B independent of knn) + acc init, fused */
    prep3_kernel<<<(NN*DD)/256, 256>>>(p_ge1, p_g3, p_sq);
    gemm_ab<<<192, 256>>>(p_xf1, W_c1, b_c1, p_A, p_B, p_acc);

    /* knn 1, then fused lp + scatter */
    knn_mma_kernel<<<knn_grid, 256, KNN_SMEM>>>(p_g3, p_sq, p_idx1);
    lp_scatter_kernel<<<2720, 256>>>(p_ge1, p_idx1, t1, lp, 0, p_A, p_B, p_acc);
    decode_relu_kernel<<<(NN*DD)/256, 256>>>(p_acc, p_x2);

    /* embed 2 on concat[ge1, x2] */
    gemm_act<64><<<NN/64, 256>>>(p_ge1, 64, p_x2, 64, W_d2, b_d2, p_ge2, 0);

    /* prep + edge-conv GEMMs for layer 2 (acc already re-initialized) */
    prep3_kernel<<<(NN*DD)/256, 256>>>(p_ge2, p_g3, p_sq);
    gemm_ab<<<128, 256>>>(p_x2, W_c2, b_c2, p_A, p_B, p_acc);

    /* knn 2, then fused lp + scatter */
    knn_mma_kernel<<<knn_grid, 256, KNN_SMEM>>>(p_g3, p_sq, p_idx2);
    lp_scatter_kernel<<<2720, 256>>>(p_ge2, p_idx2, t2, lp, 1, p_A, p_B, p_acc);

    /* head (decode fused) */
    head_kernel<<<NN/128, 128>>>(p_acc, W_f1, b_f1, W_f2, b_f2, out);
}